// round 9
// baseline (speedup 1.0000x reference)
#include <cuda_runtime.h>
#include <cstdint>

// Problem constants
#define BB 2048
#define TT 2
#define NTOK 64
#define CDIM 256
#define NH 8
#define HD 32

// Scratch (device globals; allocation APIs are forbidden)
__device__ float g_q[(size_t)BB * NTOK * CDIM];
__device__ float g_kv[(size_t)BB * TT * NTOK * 2 * CDIM];
__device__ float g_attn[(size_t)BB * TT * NTOK * CDIM];
__device__ float g_bias[NH * NTOK * NTOK];      // [h][n][m] precomputed rpb
__device__ float g_wq[CDIM * CDIM];             // tf32-pre-converted weights
__device__ float g_wkv[2 * CDIM * CDIM];
__device__ float g_wp[CDIM * CDIM];

// ---- tf32 helpers -----------------------------------------------------------
__device__ __forceinline__ uint32_t f2tf32(float f) {
    uint32_t r;
    asm("cvt.rna.tf32.f32 %0, %1;" : "=r"(r) : "f"(f));
    return r;
}
__device__ __forceinline__ void mma_tf32(float c[4], const uint32_t a[4],
                                         const uint32_t b[2]) {
    asm("mma.sync.aligned.m16n8k8.row.col.f32.tf32.tf32.f32 "
        "{%0,%1,%2,%3}, {%4,%5,%6,%7}, {%8,%9}, {%0,%1,%2,%3};"
        : "+f"(c[0]), "+f"(c[1]), "+f"(c[2]), "+f"(c[3])
        : "r"(a[0]), "r"(a[1]), "r"(a[2]), "r"(a[3]), "r"(b[0]), "r"(b[1]));
}

// ---- cp.async helpers -------------------------------------------------------
__device__ __forceinline__ void cp16(float* smem_dst, const float* gsrc) {
    uint32_t s = (uint32_t)__cvta_generic_to_shared(smem_dst);
    asm volatile("cp.async.cg.shared.global [%0], [%1], 16;" :: "r"(s), "l"(gsrc));
}
__device__ __forceinline__ void cp_commit() {
    asm volatile("cp.async.commit_group;");
}
__device__ __forceinline__ void cp_wait1() {
    asm volatile("cp.async.wait_group 1;");
}
__device__ __forceinline__ void cp_wait0() {
    asm volatile("cp.async.wait_group 0;");
}

// ---------------------------------------------------------------------------
// Bias precompute: g_bias[h][n][m] = rpb[relidx(n,m)*8 + h]
// ---------------------------------------------------------------------------
__global__ __launch_bounds__(256) void bias_precomp(const float* __restrict__ rpb)
{
    int i = blockIdx.x * 256 + threadIdx.x;   // 0..32767
    int h = i >> 12;
    int n = (i >> 6) & 63;
    int m = i & 63;
    int idx = ((n >> 3) - (m >> 3) + 7) * 15 + ((n & 7) - (m & 7) + 7);
    g_bias[i] = rpb[idx * 8 + h];
}

// Weight pre-conversion to tf32 bit patterns (stored as float)
__global__ __launch_bounds__(256) void wconv(const float* __restrict__ src,
                                             float* __restrict__ dst, int n)
{
    int i = blockIdx.x * 256 + threadIdx.x;
    if (i < n) dst[i] = __uint_as_float(f2tf32(src[i]));
}

// ---------------------------------------------------------------------------
// TF32 GEMM: C[M,N] = A[M,K] @ W[N,K]^T + bias[N].
// 128x128 block tile, BK=32, 128 threads = 4 warps of 64x64 warp-tiles
// (LDS:HMMA = 1:1, vs 1.5:1 for 64x32). W is PRE-CONVERTED tf32 (no cvt on B).
// cp.async double-buffered; A cvt at fragment load.
// ---------------------------------------------------------------------------
#define GEMM_SMEM_BYTES (4 * 128 * 36 * 4)   // 2 bufs x (A + W) x 128x36 words

__global__ __launch_bounds__(128, 2) void gemm_tf32(
    const float* __restrict__ A, const float* __restrict__ Wt,
    const float* __restrict__ bias, float* __restrict__ C,
    int M, int N, int K)
{
    extern __shared__ float gsm[];
    float* Asm = gsm;                    // [2][128*36]
    float* Wsm = gsm + 2 * 128 * 36;     // [2][128*36]

    const int tid  = threadIdx.x;
    const int wid  = tid >> 5;
    const int lane = tid & 31;
    const int g    = lane >> 2;
    const int tig  = lane & 3;
    const int bm = blockIdx.y * 128;
    const int bn = blockIdx.x * 128;
    const int warp_m = (wid & 1) * 64;
    const int warp_n = (wid >> 1) * 64;

    // staging map: thread -> rows (tid>>3)+16c, float4 col (tid&7)
    const int srow = tid >> 3;    // 0..15
    const int sc4  = (tid & 7) * 4;
    const float* Abase = A + (size_t)(bm + srow) * K + sc4;
    const float* Wbase = Wt + (size_t)(bn + srow) * K + sc4;

    float acc[4][8][4];
#pragma unroll
    for (int i = 0; i < 4; i++)
#pragma unroll
        for (int j = 0; j < 8; j++)
#pragma unroll
            for (int r = 0; r < 4; r++) acc[i][j][r] = 0.0f;

    const int nk = K >> 5;

    // prologue: stage tile 0 into buffer 0
    {
#pragma unroll
        for (int c = 0; c < 8; c++) {
            int row = srow + 16 * c;
            cp16(Asm + row * 36 + sc4, Abase + (size_t)(16 * c) * K);
            cp16(Wsm + row * 36 + sc4, Wbase + (size_t)(16 * c) * K);
        }
        cp_commit();
    }

    for (int kt = 0; kt < nk; kt++) {
        const int cur = kt & 1;
        if (kt + 1 < nk) {
            float* Ad = Asm + (1 - cur) * 128 * 36;
            float* Wd = Wsm + (1 - cur) * 128 * 36;
            const float* Ag = Abase + (kt + 1) * 32;
            const float* Wg = Wbase + (kt + 1) * 32;
#pragma unroll
            for (int c = 0; c < 8; c++) {
                int row = srow + 16 * c;
                cp16(Ad + row * 36 + sc4, Ag + (size_t)(16 * c) * K);
                cp16(Wd + row * 36 + sc4, Wg + (size_t)(16 * c) * K);
            }
            cp_commit();
            cp_wait1();
        } else {
            cp_wait0();
        }
        __syncthreads();

        const float* Ab = Asm + cur * 128 * 36;
        const float* Wb = Wsm + cur * 128 * 36;
#pragma unroll
        for (int kk = 0; kk < 4; kk++) {
            const int kb = kk * 8;
            uint32_t af[4][4], bf[8][2];
#pragma unroll
            for (int i = 0; i < 4; i++) {
                int row = warp_m + i * 16;
                af[i][0] = f2tf32(Ab[(row + g) * 36 + kb + tig]);
                af[i][1] = f2tf32(Ab[(row + 8 + g) * 36 + kb + tig]);
                af[i][2] = f2tf32(Ab[(row + g) * 36 + kb + tig + 4]);
                af[i][3] = f2tf32(Ab[(row + 8 + g) * 36 + kb + tig + 4]);
            }
#pragma unroll
            for (int j = 0; j < 8; j++) {
                int col = warp_n + j * 8 + g;
                bf[j][0] = __float_as_uint(Wb[col * 36 + kb + tig]);
                bf[j][1] = __float_as_uint(Wb[col * 36 + kb + tig + 4]);
            }
#pragma unroll
            for (int i = 0; i < 4; i++)
#pragma unroll
                for (int j = 0; j < 8; j++)
                    mma_tf32(acc[i][j], af[i], bf[j]);
        }
        __syncthreads();
    }

#pragma unroll
    for (int j = 0; j < 8; j++) {
        int col = bn + warp_n + j * 8 + tig * 2;
        float b0 = bias[col], b1 = bias[col + 1];
#pragma unroll
        for (int i = 0; i < 4; i++) {
            int row = bm + warp_m + i * 16 + g;
            float2 v0 = make_float2(acc[i][j][0] + b0, acc[i][j][1] + b1);
            float2 v1 = make_float2(acc[i][j][2] + b0, acc[i][j][3] + b1);
            *reinterpret_cast<float2*>(C + (size_t)row * N + col) = v0;
            *reinterpret_cast<float2*>(C + (size_t)(row + 8) * N + col) = v1;
        }
    }
}

// ---------------------------------------------------------------------------
// Tensor-core attention, single-pass tf32 (GEMMs are already 1x tf32; errors
// add in quadrature and stay under the 1e-3 gate).
// Block = (b, t, head-pair): 128 threads, 2 warps per head.
// Per-head smem (floats): Q[64x36] @0 (tf32 bits), K[64x36] @2304 (tf32 bits),
// V[64x40] @4608 (tf32 bits), S[64x68] @7168, inv_sum[64] @11520.
// Bias staged into dead Q/K region @0 after QK^T.
// ---------------------------------------------------------------------------
#define HEADF 11584
#define QOFF 0
#define KOFF 2304
#define VOFF 4608
#define SOFF 7168
#define SUMOFF 11520
#define PLOFF 0
#define ATTN_SMEM_BYTES (2 * HEADF * 4)

__global__ __launch_bounds__(128) void attn_mma(void)
{
    extern __shared__ float sm[];
    const int tid  = threadIdx.x;
    const int wid  = tid >> 5;
    const int lane = tid & 31;
    const int g    = lane >> 2;
    const int tig  = lane & 3;
    const int hslot = wid >> 1;
    const int whalf = wid & 1;
    const int bx = blockIdx.x;
    const int hpair = bx & 3;
    const int t = (bx >> 2) & 1;
    const int b = bx >> 3;
    const int h = hpair * 2 + hslot;
    const int th = tid & 63;

    float* S = sm + hslot * HEADF;

    // ---- stage Q (pre-scaled), K, V — converted to tf32 bits once ----
    const float scale = 0.17677669529663687f;  // 32^-0.5
    const float* qg = g_q + (size_t)(b * 64) * 256 + h * 32;
    const float* kg = g_kv + (size_t)((b * 2 + t) * 64) * 512 + h * 32;
#pragma unroll
    for (int it = 0; it < 8; it++) {
        int idx = th + 64 * it;
        int r = idx >> 3, c4 = idx & 7;
        float4 qv = *reinterpret_cast<const float4*>(qg + (size_t)r * 256 + c4 * 4);
        float4 qt;
        qt.x = __uint_as_float(f2tf32(qv.x * scale));
        qt.y = __uint_as_float(f2tf32(qv.y * scale));
        qt.z = __uint_as_float(f2tf32(qv.z * scale));
        qt.w = __uint_as_float(f2tf32(qv.w * scale));
        *reinterpret_cast<float4*>(S + QOFF + r * 36 + c4 * 4) = qt;
        float4 kv = *reinterpret_cast<const float4*>(kg + (size_t)r * 512 + c4 * 4);
        float4 kt;
        kt.x = __uint_as_float(f2tf32(kv.x));
        kt.y = __uint_as_float(f2tf32(kv.y));
        kt.z = __uint_as_float(f2tf32(kv.z));
        kt.w = __uint_as_float(f2tf32(kv.w));
        *reinterpret_cast<float4*>(S + KOFF + r * 36 + c4 * 4) = kt;
        float4 vv = *reinterpret_cast<const float4*>(kg + 256 + (size_t)r * 512 + c4 * 4);
        float4 vt;
        vt.x = __uint_as_float(f2tf32(vv.x));
        vt.y = __uint_as_float(f2tf32(vv.y));
        vt.z = __uint_as_float(f2tf32(vv.z));
        vt.w = __uint_as_float(f2tf32(vv.w));
        *reinterpret_cast<float4*>(S + VOFF + r * 40 + c4 * 4) = vt;
    }
    __syncthreads();

    // ---- QK^T : S[64x64] = Q @ K^T; warp rows 32*whalf..+31, all 64 cols ----
    {
        float acc[2][8][4];
#pragma unroll
        for (int i = 0; i < 2; i++)
#pragma unroll
            for (int j = 0; j < 8; j++)
#pragma unroll
                for (int r = 0; r < 4; r++) acc[i][j][r] = 0.0f;

#pragma unroll
        for (int k = 0; k < 4; k++) {
            uint32_t af[2][4];
#pragma unroll
            for (int i = 0; i < 2; i++) {
                int rb = (2 * whalf + i) * 16;
                const float* q0 = S + QOFF + (rb + g) * 36 + 8 * k + tig;
                const float* q1 = S + QOFF + (rb + 8 + g) * 36 + 8 * k + tig;
                af[i][0] = __float_as_uint(q0[0]);
                af[i][1] = __float_as_uint(q1[0]);
                af[i][2] = __float_as_uint(q0[4]);
                af[i][3] = __float_as_uint(q1[4]);
            }
#pragma unroll
            for (int jn = 0; jn < 8; jn++) {
                int col = jn * 8 + g;
                const float* kp = S + KOFF + col * 36 + 8 * k + tig;
                uint32_t bf[2];
                bf[0] = __float_as_uint(kp[0]);
                bf[1] = __float_as_uint(kp[4]);
#pragma unroll
                for (int i = 0; i < 2; i++)
                    mma_tf32(acc[i][jn], af[i], bf);
            }
        }
#pragma unroll
        for (int i = 0; i < 2; i++)
#pragma unroll
            for (int jn = 0; jn < 8; jn++) {
                int rb = (2 * whalf + i) * 16;
                int cb = jn * 8 + 2 * tig;
                *reinterpret_cast<float2*>(S + SOFF + (rb + g) * 68 + cb) =
                    make_float2(acc[i][jn][0], acc[i][jn][1]);
                *reinterpret_cast<float2*>(S + SOFF + (rb + 8 + g) * 68 + cb) =
                    make_float2(acc[i][jn][2], acc[i][jn][3]);
            }
    }
    __syncthreads();

    // ---- stage bias[h] (16KB) into dead Q region (coalesced float4) ----
    {
        const float* bg = g_bias + h * 4096;
#pragma unroll
        for (int it = 0; it < 16; it++) {
            int j = th + 64 * it;        // float4 id 0..1023
            int r = j >> 4, m4 = j & 15;
            float4 bv = *reinterpret_cast<const float4*>(bg + r * 64 + m4 * 4);
            *reinterpret_cast<float4*>(S + PLOFF + r * 68 + m4 * 4) = bv;
        }
    }
    __syncthreads();

    // ---- softmax: one row per thread; store P directly as tf32 bits ----
    {
        const int r = th;
        float* Sr = S + SOFF + r * 68;
        const float* Bl = S + PLOFF + r * 68;
        float mx = -1e30f;
#pragma unroll 8
        for (int m = 0; m < 64; m++) {
            float s = Sr[m] + Bl[m];
            Sr[m] = s;
            mx = fmaxf(mx, s);
        }
        float sum = 0.0f;
#pragma unroll 8
        for (int m = 0; m < 64; m++) {
            float e = __expf(Sr[m] - mx);
            sum += e;
            Sr[m] = __uint_as_float(f2tf32(e));
        }
        S[SUMOFF + r] = 1.0f / sum;
    }
    __syncthreads();

    // ---- PV : O[64x32] = P @ V ----
    float acc[2][4][4];
#pragma unroll
    for (int i = 0; i < 2; i++)
#pragma unroll
        for (int j = 0; j < 4; j++)
#pragma unroll
            for (int r = 0; r < 4; r++) acc[i][j][r] = 0.0f;

#pragma unroll
    for (int k = 0; k < 8; k++) {
        uint32_t ah[2][4];
#pragma unroll
        for (int i = 0; i < 2; i++) {
            int rb = (2 * whalf + i) * 16;
            const float* p0 = S + SOFF + (rb + g) * 68 + 8 * k + tig;
            const float* p1 = S + SOFF + (rb + 8 + g) * 68 + 8 * k + tig;
            ah[i][0] = __float_as_uint(p0[0]);
            ah[i][1] = __float_as_uint(p1[0]);
            ah[i][2] = __float_as_uint(p0[4]);
            ah[i][3] = __float_as_uint(p1[4]);
        }
        uint32_t bf[4][2];
#pragma unroll
        for (int j = 0; j < 4; j++) {
            const float* v0 = S + VOFF + (8 * k + tig) * 40 + 8 * j + g;
            const float* v1 = S + VOFF + (8 * k + tig + 4) * 40 + 8 * j + g;
            bf[j][0] = __float_as_uint(v0[0]);
            bf[j][1] = __float_as_uint(v1[0]);
        }
#pragma unroll
        for (int i = 0; i < 2; i++)
#pragma unroll
            for (int j = 0; j < 4; j++)
                mma_tf32(acc[i][j], ah[i], bf[j]);
    }

    // ---- epilogue ----
    float* og = g_attn + (size_t)((b * 2 + t) * 64) * 256 + h * 32;
#pragma unroll
    for (int i = 0; i < 2; i++) {
        int rb = (2 * whalf + i) * 16;
        float is0 = S[SUMOFF + rb + g];
        float is1 = S[SUMOFF + rb + 8 + g];
#pragma unroll
        for (int j = 0; j < 4; j++) {
            int d = 8 * j + 2 * tig;
            *reinterpret_cast<float2*>(og + (size_t)(rb + g) * 256 + d) =
                make_float2(acc[i][j][0] * is0, acc[i][j][1] * is0);
            *reinterpret_cast<float2*>(og + (size_t)(rb + 8 + g) * 256 + d) =
                make_float2(acc[i][j][2] * is1, acc[i][j][3] * is1);
        }
    }
}

// ---------------------------------------------------------------------------
extern "C" void kernel_launch(void* const* d_in, const int* in_sizes, int n_in,
                              void* d_out, int out_size)
{
    const float* x      = (const float*)d_in[0];
    const float* memory = (const float*)d_in[1];
    const float* q_w    = (const float*)d_in[2];
    const float* q_b    = (const float*)d_in[3];
    const float* kv_w   = (const float*)d_in[4];
    const float* kv_b   = (const float*)d_in[5];
    const float* proj_w = (const float*)d_in[6];
    const float* proj_b = (const float*)d_in[7];
    const float* rpb    = (const float*)d_in[8];
    float* out = (float*)d_out;

    float *pq, *pkv, *pattn, *pwq, *pwkv, *pwp;
    cudaGetSymbolAddress((void**)&pq, g_q);
    cudaGetSymbolAddress((void**)&pkv, g_kv);
    cudaGetSymbolAddress((void**)&pattn, g_attn);
    cudaGetSymbolAddress((void**)&pwq, g_wq);
    cudaGetSymbolAddress((void**)&pwkv, g_wkv);
    cudaGetSymbolAddress((void**)&pwp, g_wp);

    cudaFuncSetAttribute(gemm_tf32, cudaFuncAttributeMaxDynamicSharedMemorySize,
                         GEMM_SMEM_BYTES);
    cudaFuncSetAttribute(attn_mma, cudaFuncAttributeMaxDynamicSharedMemorySize,
                         ATTN_SMEM_BYTES);

    bias_precomp<<<128, 256>>>(rpb);
    wconv<<<(CDIM * CDIM + 255) / 256, 256>>>(q_w, pwq, CDIM * CDIM);
    wconv<<<(2 * CDIM * CDIM + 255) / 256, 256>>>(kv_w, pwkv, 2 * CDIM * CDIM);
    wconv<<<(CDIM * CDIM + 255) / 256, 256>>>(proj_w, pwp, CDIM * CDIM);

    // q = x @ q_w^T + q_b              (131072 x 256, K=256)
    gemm_tf32<<<dim3(2, 1024), 128, GEMM_SMEM_BYTES>>>(x, pwq, q_b, pq, BB * NTOK, CDIM, CDIM);
    // kv = memory @ kv_w^T + kv_b      (262144 x 512, K=256)
    gemm_tf32<<<dim3(4, 2048), 128, GEMM_SMEM_BYTES>>>(memory, pwkv, kv_b, pkv, BB * TT * NTOK, 2 * CDIM, CDIM);
    // attention: block = (b, t, head-pair)
    attn_mma<<<BB * TT * (NH / 2), 128, ATTN_SMEM_BYTES>>>();
    // out = attn @ proj_w^T + proj_b   (262144 x 256, K=256)
    gemm_tf32<<<dim3(2, 2048), 128, GEMM_SMEM_BYTES>>>(pattn, pwp, proj_b, out, BB * TT * NTOK, CDIM, CDIM);
}

// round 11
// speedup vs baseline: 1.4686x; 1.4686x over previous
#include <cuda_runtime.h>
#include <cstdint>

// Problem constants
#define BB 2048
#define TT 2
#define NTOK 64
#define CDIM 256
#define NH 8
#define HD 32

// Scratch (device globals; allocation APIs are forbidden)
__device__ float g_q[(size_t)BB * NTOK * CDIM];
__device__ float g_kv[(size_t)BB * TT * NTOK * 2 * CDIM];
__device__ float g_attn[(size_t)BB * TT * NTOK * CDIM];
__device__ float g_bias[NH * NTOK * NTOK];      // [h][n][m] precomputed rpb
__device__ float g_wq[CDIM * CDIM];             // tf32-pre-converted weights
__device__ float g_wkv[2 * CDIM * CDIM];
__device__ float g_wp[CDIM * CDIM];

// ---- tf32 helpers -----------------------------------------------------------
__device__ __forceinline__ uint32_t f2tf32(float f) {
    uint32_t r;
    asm("cvt.rna.tf32.f32 %0, %1;" : "=r"(r) : "f"(f));
    return r;
}
__device__ __forceinline__ void mma_tf32(float c[4], const uint32_t a[4],
                                         const uint32_t b[2]) {
    asm("mma.sync.aligned.m16n8k8.row.col.f32.tf32.tf32.f32 "
        "{%0,%1,%2,%3}, {%4,%5,%6,%7}, {%8,%9}, {%0,%1,%2,%3};"
        : "+f"(c[0]), "+f"(c[1]), "+f"(c[2]), "+f"(c[3])
        : "r"(a[0]), "r"(a[1]), "r"(a[2]), "r"(a[3]), "r"(b[0]), "r"(b[1]));
}

// ---- cp.async helpers -------------------------------------------------------
__device__ __forceinline__ void cp16(float* smem_dst, const float* gsrc) {
    uint32_t s = (uint32_t)__cvta_generic_to_shared(smem_dst);
    asm volatile("cp.async.cg.shared.global [%0], [%1], 16;" :: "r"(s), "l"(gsrc));
}
__device__ __forceinline__ void cp_commit() {
    asm volatile("cp.async.commit_group;");
}
__device__ __forceinline__ void cp_wait1() {
    asm volatile("cp.async.wait_group 1;");
}
__device__ __forceinline__ void cp_wait0() {
    asm volatile("cp.async.wait_group 0;");
}

// ---------------------------------------------------------------------------
// Bias precompute: g_bias[h][n][m] = rpb[relidx(n,m)*8 + h]
// ---------------------------------------------------------------------------
__global__ __launch_bounds__(256) void bias_precomp(const float* __restrict__ rpb)
{
    int i = blockIdx.x * 256 + threadIdx.x;   // 0..32767
    int h = i >> 12;
    int n = (i >> 6) & 63;
    int m = i & 63;
    int idx = ((n >> 3) - (m >> 3) + 7) * 15 + ((n & 7) - (m & 7) + 7);
    g_bias[i] = rpb[idx * 8 + h];
}

// Weight pre-conversion to tf32 bit patterns (stored as float)
__global__ __launch_bounds__(256) void wconv(const float* __restrict__ src,
                                             float* __restrict__ dst, int n)
{
    int i = blockIdx.x * 256 + threadIdx.x;
    if (i < n) dst[i] = __uint_as_float(f2tf32(src[i]));
}

// ---------------------------------------------------------------------------
// TF32 GEMM (round-8 proven config): C[M,N] = A[M,K] @ W[N,K]^T + bias[N].
// 128x128 block tile, BK=32, 256 threads = 8 warps of 64x32 warp-tiles.
// cp.async double-buffered. W is PRE-CONVERTED tf32 (no cvt on B fragments);
// A cvt at fragment load.
// ---------------------------------------------------------------------------
#define GEMM_SMEM_BYTES (4 * 128 * 36 * 4)   // 2 bufs x (A + W) x 128x36 words

__global__ __launch_bounds__(256, 2) void gemm_tf32(
    const float* __restrict__ A, const float* __restrict__ Wt,
    const float* __restrict__ bias, float* __restrict__ C,
    int M, int N, int K)
{
    extern __shared__ float gsm[];
    float* Asm = gsm;                    // [2][128*36]
    float* Wsm = gsm + 2 * 128 * 36;     // [2][128*36]

    const int tid  = threadIdx.x;
    const int wid  = tid >> 5;
    const int lane = tid & 31;
    const int g    = lane >> 2;
    const int tig  = lane & 3;
    const int bm = blockIdx.y * 128;
    const int bn = blockIdx.x * 128;
    const int warp_m = (wid & 1) * 64;
    const int warp_n = (wid >> 1) * 32;

    const int sr  = tid >> 3;   // 0..31
    const int sk4 = (tid & 7) * 4;
    const float* Abase = A + (size_t)(bm + sr) * K + sk4;
    const float* Wbase = Wt + (size_t)(bn + sr) * K + sk4;

    float acc[4][4][4];
#pragma unroll
    for (int i = 0; i < 4; i++)
#pragma unroll
        for (int j = 0; j < 4; j++)
#pragma unroll
            for (int r = 0; r < 4; r++) acc[i][j][r] = 0.0f;

    const int nk = K >> 5;

    // prologue: stage tile 0 into buffer 0
    {
#pragma unroll
        for (int it = 0; it < 4; it++) {
            int row = sr + it * 32;
            cp16(Asm + row * 36 + sk4, Abase + (size_t)(it * 32) * K);
            cp16(Wsm + row * 36 + sk4, Wbase + (size_t)(it * 32) * K);
        }
        cp_commit();
    }

    for (int kt = 0; kt < nk; kt++) {
        const int cur = kt & 1;
        if (kt + 1 < nk) {
            float* Ad = Asm + (1 - cur) * 128 * 36;
            float* Wd = Wsm + (1 - cur) * 128 * 36;
            const float* Ag = Abase + (kt + 1) * 32;
            const float* Wg = Wbase + (kt + 1) * 32;
#pragma unroll
            for (int it = 0; it < 4; it++) {
                int row = sr + it * 32;
                cp16(Ad + row * 36 + sk4, Ag + (size_t)(it * 32) * K);
                cp16(Wd + row * 36 + sk4, Wg + (size_t)(it * 32) * K);
            }
            cp_commit();
            cp_wait1();
        } else {
            cp_wait0();
        }
        __syncthreads();

        const float* Ab = Asm + cur * 128 * 36;
        const float* Wb = Wsm + cur * 128 * 36;
#pragma unroll
        for (int kk = 0; kk < 4; kk++) {
            const int kb = kk * 8;
            uint32_t af[4][4], bf[4][2];
#pragma unroll
            for (int i = 0; i < 4; i++) {
                int row = warp_m + i * 16;
                af[i][0] = f2tf32(Ab[(row + g) * 36 + kb + tig]);
                af[i][1] = f2tf32(Ab[(row + 8 + g) * 36 + kb + tig]);
                af[i][2] = f2tf32(Ab[(row + g) * 36 + kb + tig + 4]);
                af[i][3] = f2tf32(Ab[(row + 8 + g) * 36 + kb + tig + 4]);
            }
#pragma unroll
            for (int j = 0; j < 4; j++) {
                int col = warp_n + j * 8 + g;
                bf[j][0] = __float_as_uint(Wb[col * 36 + kb + tig]);
                bf[j][1] = __float_as_uint(Wb[col * 36 + kb + tig + 4]);
            }
#pragma unroll
            for (int i = 0; i < 4; i++)
#pragma unroll
                for (int j = 0; j < 4; j++)
                    mma_tf32(acc[i][j], af[i], bf[j]);
        }
        __syncthreads();
    }

#pragma unroll
    for (int j = 0; j < 4; j++) {
        int col = bn + warp_n + j * 8 + tig * 2;
        float b0 = bias[col], b1 = bias[col + 1];
#pragma unroll
        for (int i = 0; i < 4; i++) {
            int row = bm + warp_m + i * 16 + g;
            float2 v0 = make_float2(acc[i][j][0] + b0, acc[i][j][1] + b1);
            float2 v1 = make_float2(acc[i][j][2] + b0, acc[i][j][3] + b1);
            *reinterpret_cast<float2*>(C + (size_t)row * N + col) = v0;
            *reinterpret_cast<float2*>(C + (size_t)(row + 8) * N + col) = v1;
        }
    }
}

// ---------------------------------------------------------------------------
// Tensor-core attention, single-pass tf32 (round-9 version, kept).
// Block = (b, t, head-pair): 128 threads, 2 warps per head.
// Per-head smem (floats): Q[64x36] @0 (tf32 bits), K[64x36] @2304 (tf32 bits),
// V[64x40] @4608 (tf32 bits), S[64x68] @7168, inv_sum[64] @11520.
// Bias staged into dead Q/K region @0 after QK^T.
// ---------------------------------------------------------------------------
#define HEADF 11584
#define QOFF 0
#define KOFF 2304
#define VOFF 4608
#define SOFF 7168
#define SUMOFF 11520
#define PLOFF 0
#define ATTN_SMEM_BYTES (2 * HEADF * 4)

__global__ __launch_bounds__(128) void attn_mma(void)
{
    extern __shared__ float sm[];
    const int tid  = threadIdx.x;
    const int wid  = tid >> 5;
    const int lane = tid & 31;
    const int g    = lane >> 2;
    const int tig  = lane & 3;
    const int hslot = wid >> 1;
    const int whalf = wid & 1;
    const int bx = blockIdx.x;
    const int hpair = bx & 3;
    const int t = (bx >> 2) & 1;
    const int b = bx >> 3;
    const int h = hpair * 2 + hslot;
    const int th = tid & 63;

    float* S = sm + hslot * HEADF;

    // ---- stage Q (pre-scaled), K, V — converted to tf32 bits once ----
    const float scale = 0.17677669529663687f;  // 32^-0.5
    const float* qg = g_q + (size_t)(b * 64) * 256 + h * 32;
    const float* kg = g_kv + (size_t)((b * 2 + t) * 64) * 512 + h * 32;
#pragma unroll
    for (int it = 0; it < 8; it++) {
        int idx = th + 64 * it;
        int r = idx >> 3, c4 = idx & 7;
        float4 qv = *reinterpret_cast<const float4*>(qg + (size_t)r * 256 + c4 * 4);
        float4 qt;
        qt.x = __uint_as_float(f2tf32(qv.x * scale));
        qt.y = __uint_as_float(f2tf32(qv.y * scale));
        qt.z = __uint_as_float(f2tf32(qv.z * scale));
        qt.w = __uint_as_float(f2tf32(qv.w * scale));
        *reinterpret_cast<float4*>(S + QOFF + r * 36 + c4 * 4) = qt;
        float4 kv = *reinterpret_cast<const float4*>(kg + (size_t)r * 512 + c4 * 4);
        float4 kt;
        kt.x = __uint_as_float(f2tf32(kv.x));
        kt.y = __uint_as_float(f2tf32(kv.y));
        kt.z = __uint_as_float(f2tf32(kv.z));
        kt.w = __uint_as_float(f2tf32(kv.w));
        *reinterpret_cast<float4*>(S + KOFF + r * 36 + c4 * 4) = kt;
        float4 vv = *reinterpret_cast<const float4*>(kg + 256 + (size_t)r * 512 + c4 * 4);
        float4 vt;
        vt.x = __uint_as_float(f2tf32(vv.x));
        vt.y = __uint_as_float(f2tf32(vv.y));
        vt.z = __uint_as_float(f2tf32(vv.z));
        vt.w = __uint_as_float(f2tf32(vv.w));
        *reinterpret_cast<float4*>(S + VOFF + r * 40 + c4 * 4) = vt;
    }
    __syncthreads();

    // ---- QK^T : S[64x64] = Q @ K^T; warp rows 32*whalf..+31, all 64 cols ----
    {
        float acc[2][8][4];
#pragma unroll
        for (int i = 0; i < 2; i++)
#pragma unroll
            for (int j = 0; j < 8; j++)
#pragma unroll
                for (int r = 0; r < 4; r++) acc[i][j][r] = 0.0f;

#pragma unroll
        for (int k = 0; k < 4; k++) {
            uint32_t af[2][4];
#pragma unroll
            for (int i = 0; i < 2; i++) {
                int rb = (2 * whalf + i) * 16;
                const float* q0 = S + QOFF + (rb + g) * 36 + 8 * k + tig;
                const float* q1 = S + QOFF + (rb + 8 + g) * 36 + 8 * k + tig;
                af[i][0] = __float_as_uint(q0[0]);
                af[i][1] = __float_as_uint(q1[0]);
                af[i][2] = __float_as_uint(q0[4]);
                af[i][3] = __float_as_uint(q1[4]);
            }
#pragma unroll
            for (int jn = 0; jn < 8; jn++) {
                int col = jn * 8 + g;
                const float* kp = S + KOFF + col * 36 + 8 * k + tig;
                uint32_t bf[2];
                bf[0] = __float_as_uint(kp[0]);
                bf[1] = __float_as_uint(kp[4]);
#pragma unroll
                for (int i = 0; i < 2; i++)
                    mma_tf32(acc[i][jn], af[i], bf);
            }
        }
#pragma unroll
        for (int i = 0; i < 2; i++)
#pragma unroll
            for (int jn = 0; jn < 8; jn++) {
                int rb = (2 * whalf + i) * 16;
                int cb = jn * 8 + 2 * tig;
                *reinterpret_cast<float2*>(S + SOFF + (rb + g) * 68 + cb) =
                    make_float2(acc[i][jn][0], acc[i][jn][1]);
                *reinterpret_cast<float2*>(S + SOFF + (rb + 8 + g) * 68 + cb) =
                    make_float2(acc[i][jn][2], acc[i][jn][3]);
            }
    }
    __syncthreads();

    // ---- stage bias[h] (16KB) into dead Q region (coalesced float4) ----
    {
        const float* bg = g_bias + h * 4096;
#pragma unroll
        for (int it = 0; it < 16; it++) {
            int j = th + 64 * it;        // float4 id 0..1023
            int r = j >> 4, m4 = j & 15;
            float4 bv = *reinterpret_cast<const float4*>(bg + r * 64 + m4 * 4);
            *reinterpret_cast<float4*>(S + PLOFF + r * 68 + m4 * 4) = bv;
        }
    }
    __syncthreads();

    // ---- softmax: one row per thread; store P directly as tf32 bits ----
    {
        const int r = th;
        float* Sr = S + SOFF + r * 68;
        const float* Bl = S + PLOFF + r * 68;
        float mx = -1e30f;
#pragma unroll 8
        for (int m = 0; m < 64; m++) {
            float s = Sr[m] + Bl[m];
            Sr[m] = s;
            mx = fmaxf(mx, s);
        }
        float sum = 0.0f;
#pragma unroll 8
        for (int m = 0; m < 64; m++) {
            float e = __expf(Sr[m] - mx);
            sum += e;
            Sr[m] = __uint_as_float(f2tf32(e));
        }
        S[SUMOFF + r] = 1.0f / sum;
    }
    __syncthreads();

    // ---- PV : O[64x32] = P @ V ----
    float acc[2][4][4];
#pragma unroll
    for (int i = 0; i < 2; i++)
#pragma unroll
        for (int j = 0; j < 4; j++)
#pragma unroll
            for (int r = 0; r < 4; r++) acc[i][j][r] = 0.0f;

#pragma unroll
    for (int k = 0; k < 8; k++) {
        uint32_t ah[2][4];
#pragma unroll
        for (int i = 0; i < 2; i++) {
            int rb = (2 * whalf + i) * 16;
            const float* p0 = S + SOFF + (rb + g) * 68 + 8 * k + tig;
            const float* p1 = S + SOFF + (rb + 8 + g) * 68 + 8 * k + tig;
            ah[i][0] = __float_as_uint(p0[0]);
            ah[i][1] = __float_as_uint(p1[0]);
            ah[i][2] = __float_as_uint(p0[4]);
            ah[i][3] = __float_as_uint(p1[4]);
        }
        uint32_t bf[4][2];
#pragma unroll
        for (int j = 0; j < 4; j++) {
            const float* v0 = S + VOFF + (8 * k + tig) * 40 + 8 * j + g;
            const float* v1 = S + VOFF + (8 * k + tig + 4) * 40 + 8 * j + g;
            bf[j][0] = __float_as_uint(v0[0]);
            bf[j][1] = __float_as_uint(v1[0]);
        }
#pragma unroll
        for (int i = 0; i < 2; i++)
#pragma unroll
            for (int j = 0; j < 4; j++)
                mma_tf32(acc[i][j], ah[i], bf[j]);
    }

    // ---- epilogue ----
    float* og = g_attn + (size_t)((b * 2 + t) * 64) * 256 + h * 32;
#pragma unroll
    for (int i = 0; i < 2; i++) {
        int rb = (2 * whalf + i) * 16;
        float is0 = S[SUMOFF + rb + g];
        float is1 = S[SUMOFF + rb + 8 + g];
#pragma unroll
        for (int j = 0; j < 4; j++) {
            int d = 8 * j + 2 * tig;
            *reinterpret_cast<float2*>(og + (size_t)(rb + g) * 256 + d) =
                make_float2(acc[i][j][0] * is0, acc[i][j][1] * is0);
            *reinterpret_cast<float2*>(og + (size_t)(rb + 8 + g) * 256 + d) =
                make_float2(acc[i][j][2] * is1, acc[i][j][3] * is1);
        }
    }
}

// ---------------------------------------------------------------------------
extern "C" void kernel_launch(void* const* d_in, const int* in_sizes, int n_in,
                              void* d_out, int out_size)
{
    const float* x      = (const float*)d_in[0];
    const float* memory = (const float*)d_in[1];
    const float* q_w    = (const float*)d_in[2];
    const float* q_b    = (const float*)d_in[3];
    const float* kv_w   = (const float*)d_in[4];
    const float* kv_b   = (const float*)d_in[5];
    const float* proj_w = (const float*)d_in[6];
    const float* proj_b = (const float*)d_in[7];
    const float* rpb    = (const float*)d_in[8];
    float* out = (float*)d_out;

    float *pq, *pkv, *pattn, *pwq, *pwkv, *pwp;
    cudaGetSymbolAddress((void**)&pq, g_q);
    cudaGetSymbolAddress((void**)&pkv, g_kv);
    cudaGetSymbolAddress((void**)&pattn, g_attn);
    cudaGetSymbolAddress((void**)&pwq, g_wq);
    cudaGetSymbolAddress((void**)&pwkv, g_wkv);
    cudaGetSymbolAddress((void**)&pwp, g_wp);

    cudaFuncSetAttribute(gemm_tf32, cudaFuncAttributeMaxDynamicSharedMemorySize,
                         GEMM_SMEM_BYTES);
    cudaFuncSetAttribute(attn_mma, cudaFuncAttributeMaxDynamicSharedMemorySize,
                         ATTN_SMEM_BYTES);

    bias_precomp<<<128, 256>>>(rpb);
    wconv<<<(CDIM * CDIM + 255) / 256, 256>>>(q_w, pwq, CDIM * CDIM);
    wconv<<<(2 * CDIM * CDIM + 255) / 256, 256>>>(kv_w, pwkv, 2 * CDIM * CDIM);
    wconv<<<(CDIM * CDIM + 255) / 256, 256>>>(proj_w, pwp, CDIM * CDIM);

    // q = x @ q_w^T + q_b              (131072 x 256, K=256)
    gemm_tf32<<<dim3(2, 1024), 256, GEMM_SMEM_BYTES>>>(x, pwq, q_b, pq, BB * NTOK, CDIM, CDIM);
    // kv = memory @ kv_w^T + kv_b      (262144 x 512, K=256)
    gemm_tf32<<<dim3(4, 2048), 256, GEMM_SMEM_BYTES>>>(memory, pwkv, kv_b, pkv, BB * TT * NTOK, 2 * CDIM, CDIM);
    // attention: block = (b, t, head-pair)
    attn_mma<<<BB * TT * (NH / 2), 128, ATTN_SMEM_BYTES>>>();
    // out = attn @ proj_w^T + proj_b   (262144 x 256, K=256)
    gemm_tf32<<<dim3(2, 2048), 256, GEMM_SMEM_BYTES>>>(pattn, pwp, proj_b, out, BB * TT * NTOK, CDIM, CDIM);
}

// round 13
// speedup vs baseline: 1.6643x; 1.1333x over previous
#include <cuda_runtime.h>
#include <cstdint>

// Problem constants
#define BB 2048
#define TT 2
#define NTOK 64
#define CDIM 256
#define NH 8
#define HD 32

// Scratch (device globals; allocation APIs are forbidden)
__device__ float g_q[(size_t)BB * NTOK * CDIM];
__device__ float g_kv[(size_t)BB * TT * NTOK * 2 * CDIM];
__device__ float g_attn[(size_t)BB * TT * NTOK * CDIM];
__device__ float g_bias[NH * NTOK * NTOK];      // [h][n][m] precomputed rpb
__device__ float g_wq[CDIM * CDIM];             // tf32-pre-converted weights
__device__ float g_wkv[2 * CDIM * CDIM];
__device__ float g_wp[CDIM * CDIM];

// ---- tf32 helpers -----------------------------------------------------------
__device__ __forceinline__ uint32_t f2tf32(float f) {
    uint32_t r;
    asm("cvt.rna.tf32.f32 %0, %1;" : "=r"(r) : "f"(f));
    return r;
}
__device__ __forceinline__ void mma_tf32(float c[4], const uint32_t a[4],
                                         const uint32_t b[2]) {
    asm("mma.sync.aligned.m16n8k8.row.col.f32.tf32.tf32.f32 "
        "{%0,%1,%2,%3}, {%4,%5,%6,%7}, {%8,%9}, {%0,%1,%2,%3};"
        : "+f"(c[0]), "+f"(c[1]), "+f"(c[2]), "+f"(c[3])
        : "r"(a[0]), "r"(a[1]), "r"(a[2]), "r"(a[3]), "r"(b[0]), "r"(b[1]));
}

// ---- cp.async helpers -------------------------------------------------------
__device__ __forceinline__ void cp16(float* smem_dst, const float* gsrc) {
    uint32_t s = (uint32_t)__cvta_generic_to_shared(smem_dst);
    asm volatile("cp.async.cg.shared.global [%0], [%1], 16;" :: "r"(s), "l"(gsrc));
}
__device__ __forceinline__ void cp_commit() {
    asm volatile("cp.async.commit_group;");
}
__device__ __forceinline__ void cp_wait1() {
    asm volatile("cp.async.wait_group 1;");
}
__device__ __forceinline__ void cp_wait0() {
    asm volatile("cp.async.wait_group 0;");
}

// ---------------------------------------------------------------------------
// Bias precompute: g_bias[h][n][m] = rpb[relidx(n,m)*8 + h]
// ---------------------------------------------------------------------------
__global__ __launch_bounds__(256) void bias_precomp(const float* __restrict__ rpb)
{
    int i = blockIdx.x * 256 + threadIdx.x;   // 0..32767
    int h = i >> 12;
    int n = (i >> 6) & 63;
    int m = i & 63;
    int idx = ((n >> 3) - (m >> 3) + 7) * 15 + ((n & 7) - (m & 7) + 7);
    g_bias[i] = rpb[idx * 8 + h];
}

// Weight pre-conversion to tf32 bit patterns (stored as float)
__global__ __launch_bounds__(256) void wconv(const float* __restrict__ src,
                                             float* __restrict__ dst, int n)
{
    int i = blockIdx.x * 256 + threadIdx.x;
    if (i < n) dst[i] = __uint_as_float(f2tf32(src[i]));
}

// ---------------------------------------------------------------------------
// TF32 GEMM: C[M,N] = A[M,K] @ W[N,K]^T + bias[N].
// 256x128 block tile, BK=32, 256 threads = 8 warps as 4M x 2N, 64x64 warp
// tiles (LDS:HMMA = 1:1 at block level). cp.async double-buffered.
// W is PRE-CONVERTED tf32; A cvt at fragment load.
// ---------------------------------------------------------------------------
#define A_TW (256 * 36)
#define W_TW (128 * 36)
#define GEMM_SMEM_BYTES (2 * (A_TW + W_TW) * 4)   // 110,592 B

__global__ __launch_bounds__(256, 1) void gemm_tf32(
    const float* __restrict__ A, const float* __restrict__ Wt,
    const float* __restrict__ bias, float* __restrict__ C,
    int M, int N, int K)
{
    extern __shared__ float gsm[];
    float* Asm = gsm;                 // [2][256*36]
    float* Wsm = gsm + 2 * A_TW;      // [2][128*36]

    const int tid  = threadIdx.x;
    const int wid  = tid >> 5;
    const int lane = tid & 31;
    const int g    = lane >> 2;
    const int tig  = lane & 3;
    const int bm = blockIdx.y * 256;
    const int bn = blockIdx.x * 128;
    const int warp_m = (wid >> 1) * 64;
    const int warp_n = (wid & 1) * 64;

    const int srow = tid >> 3;        // 0..31
    const int sc4  = (tid & 7) * 4;
    const float* Abase = A + (size_t)(bm + srow) * K + sc4;
    const float* Wbase = Wt + (size_t)(bn + srow) * K + sc4;

    float acc[4][8][4];
#pragma unroll
    for (int i = 0; i < 4; i++)
#pragma unroll
        for (int j = 0; j < 8; j++)
#pragma unroll
            for (int r = 0; r < 4; r++) acc[i][j][r] = 0.0f;

    const int nk = K >> 5;

    // prologue: stage tile 0 into buffer 0
    {
#pragma unroll
        for (int c = 0; c < 8; c++)
            cp16(Asm + (srow + 32 * c) * 36 + sc4, Abase + (size_t)(32 * c) * K);
#pragma unroll
        for (int c = 0; c < 4; c++)
            cp16(Wsm + (srow + 32 * c) * 36 + sc4, Wbase + (size_t)(32 * c) * K);
        cp_commit();
    }

    for (int kt = 0; kt < nk; kt++) {
        const int cur = kt & 1;
        if (kt + 1 < nk) {
            float* Ad = Asm + (1 - cur) * A_TW;
            float* Wd = Wsm + (1 - cur) * W_TW;
            const float* Ag = Abase + (kt + 1) * 32;
            const float* Wg = Wbase + (kt + 1) * 32;
#pragma unroll
            for (int c = 0; c < 8; c++)
                cp16(Ad + (srow + 32 * c) * 36 + sc4, Ag + (size_t)(32 * c) * K);
#pragma unroll
            for (int c = 0; c < 4; c++)
                cp16(Wd + (srow + 32 * c) * 36 + sc4, Wg + (size_t)(32 * c) * K);
            cp_commit();
            cp_wait1();
        } else {
            cp_wait0();
        }
        __syncthreads();

        const float* Ab = Asm + cur * A_TW;
        const float* Wb = Wsm + cur * W_TW;
#pragma unroll
        for (int kk = 0; kk < 4; kk++) {
            const int kb = kk * 8;
            uint32_t af[4][4], bf[8][2];
#pragma unroll
            for (int i = 0; i < 4; i++) {
                int row = warp_m + i * 16;
                af[i][0] = f2tf32(Ab[(row + g) * 36 + kb + tig]);
                af[i][1] = f2tf32(Ab[(row + 8 + g) * 36 + kb + tig]);
                af[i][2] = f2tf32(Ab[(row + g) * 36 + kb + tig + 4]);
                af[i][3] = f2tf32(Ab[(row + 8 + g) * 36 + kb + tig + 4]);
            }
#pragma unroll
            for (int j = 0; j < 8; j++) {
                int col = warp_n + j * 8 + g;
                bf[j][0] = __float_as_uint(Wb[col * 36 + kb + tig]);
                bf[j][1] = __float_as_uint(Wb[col * 36 + kb + tig + 4]);
            }
#pragma unroll
            for (int i = 0; i < 4; i++)
#pragma unroll
                for (int j = 0; j < 8; j++)
                    mma_tf32(acc[i][j], af[i], bf[j]);
        }
        __syncthreads();
    }

#pragma unroll
    for (int j = 0; j < 8; j++) {
        int col = bn + warp_n + j * 8 + tig * 2;
        float b0 = bias[col], b1 = bias[col + 1];
#pragma unroll
        for (int i = 0; i < 4; i++) {
            int row = bm + warp_m + i * 16 + g;
            float2 v0 = make_float2(acc[i][j][0] + b0, acc[i][j][1] + b1);
            float2 v1 = make_float2(acc[i][j][2] + b0, acc[i][j][3] + b1);
            *reinterpret_cast<float2*>(C + (size_t)row * N + col) = v0;
            *reinterpret_cast<float2*>(C + (size_t)(row + 8) * N + col) = v1;
        }
    }
}

// ---------------------------------------------------------------------------
// Tensor-core attention, single-pass tf32.
// Block = (b, t, head-pair): 128 threads, 2 warps per head.
// Per-head smem (floats): Q[64x36] @0 (tf32 bits), K[64x36] @2304 (tf32 bits),
// V[64x40] @4608 (tf32 bits), S[64x68] @7168, inv_sum[64] @11520.
// Bias added in QK epilogue via __ldg from L2-resident g_bias.
// ---------------------------------------------------------------------------
#define HEADF 11584
#define QOFF 0
#define KOFF 2304
#define VOFF 4608
#define SOFF 7168
#define SUMOFF 11520
#define ATTN_SMEM_BYTES (2 * HEADF * 4)

__global__ __launch_bounds__(128) void attn_mma(void)
{
    extern __shared__ float sm[];
    const int tid  = threadIdx.x;
    const int wid  = tid >> 5;
    const int lane = tid & 31;
    const int g    = lane >> 2;
    const int tig  = lane & 3;
    const int hslot = wid >> 1;
    const int whalf = wid & 1;
    const int bx = blockIdx.x;
    const int hpair = bx & 3;
    const int t = (bx >> 2) & 1;
    const int b = bx >> 3;
    const int h = hpair * 2 + hslot;
    const int th = tid & 63;

    float* S = sm + hslot * HEADF;

    // ---- stage Q (pre-scaled), K, V — converted to tf32 bits once ----
    const float scale = 0.17677669529663687f;  // 32^-0.5
    const float* qg = g_q + (size_t)(b * 64) * 256 + h * 32;
    const float* kg = g_kv + (size_t)((b * 2 + t) * 64) * 512 + h * 32;
#pragma unroll
    for (int it = 0; it < 8; it++) {
        int idx = th + 64 * it;
        int r = idx >> 3, c4 = idx & 7;
        float4 qv = *reinterpret_cast<const float4*>(qg + (size_t)r * 256 + c4 * 4);
        float4 qt;
        qt.x = __uint_as_float(f2tf32(qv.x * scale));
        qt.y = __uint_as_float(f2tf32(qv.y * scale));
        qt.z = __uint_as_float(f2tf32(qv.z * scale));
        qt.w = __uint_as_float(f2tf32(qv.w * scale));
        *reinterpret_cast<float4*>(S + QOFF + r * 36 + c4 * 4) = qt;
        float4 kv = *reinterpret_cast<const float4*>(kg + (size_t)r * 512 + c4 * 4);
        float4 kt;
        kt.x = __uint_as_float(f2tf32(kv.x));
        kt.y = __uint_as_float(f2tf32(kv.y));
        kt.z = __uint_as_float(f2tf32(kv.z));
        kt.w = __uint_as_float(f2tf32(kv.w));
        *reinterpret_cast<float4*>(S + KOFF + r * 36 + c4 * 4) = kt;
        float4 vv = *reinterpret_cast<const float4*>(kg + 256 + (size_t)r * 512 + c4 * 4);
        float4 vt;
        vt.x = __uint_as_float(f2tf32(vv.x));
        vt.y = __uint_as_float(f2tf32(vv.y));
        vt.z = __uint_as_float(f2tf32(vv.z));
        vt.w = __uint_as_float(f2tf32(vv.w));
        *reinterpret_cast<float4*>(S + VOFF + r * 40 + c4 * 4) = vt;
    }
    __syncthreads();

    // ---- QK^T : S[64x64] = Q @ K^T (+bias); warp rows 32*whalf..+31 ----
    {
        float acc[2][8][4];
#pragma unroll
        for (int i = 0; i < 2; i++)
#pragma unroll
            for (int j = 0; j < 8; j++)
#pragma unroll
                for (int r = 0; r < 4; r++) acc[i][j][r] = 0.0f;

#pragma unroll
        for (int k = 0; k < 4; k++) {
            uint32_t af[2][4];
#pragma unroll
            for (int i = 0; i < 2; i++) {
                int rb = (2 * whalf + i) * 16;
                const float* q0 = S + QOFF + (rb + g) * 36 + 8 * k + tig;
                const float* q1 = S + QOFF + (rb + 8 + g) * 36 + 8 * k + tig;
                af[i][0] = __float_as_uint(q0[0]);
                af[i][1] = __float_as_uint(q1[0]);
                af[i][2] = __float_as_uint(q0[4]);
                af[i][3] = __float_as_uint(q1[4]);
            }
#pragma unroll
            for (int jn = 0; jn < 8; jn++) {
                int col = jn * 8 + g;
                const float* kp = S + KOFF + col * 36 + 8 * k + tig;
                uint32_t bf[2];
                bf[0] = __float_as_uint(kp[0]);
                bf[1] = __float_as_uint(kp[4]);
#pragma unroll
                for (int i = 0; i < 2; i++)
                    mma_tf32(acc[i][jn], af[i], bf);
            }
        }
        // store S with bias added from L2-resident table
        const float* bh = g_bias + h * 4096;
#pragma unroll
        for (int i = 0; i < 2; i++)
#pragma unroll
            for (int jn = 0; jn < 8; jn++) {
                int rb = (2 * whalf + i) * 16;
                int cb = jn * 8 + 2 * tig;
                float2 bv0 = __ldg(reinterpret_cast<const float2*>(bh + (rb + g) * 64 + cb));
                float2 bv1 = __ldg(reinterpret_cast<const float2*>(bh + (rb + 8 + g) * 64 + cb));
                *reinterpret_cast<float2*>(S + SOFF + (rb + g) * 68 + cb) =
                    make_float2(acc[i][jn][0] + bv0.x, acc[i][jn][1] + bv0.y);
                *reinterpret_cast<float2*>(S + SOFF + (rb + 8 + g) * 68 + cb) =
                    make_float2(acc[i][jn][2] + bv1.x, acc[i][jn][3] + bv1.y);
            }
    }
    __syncthreads();

    // ---- softmax: one row per thread; store P directly as tf32 bits ----
    {
        const int r = th;
        float* Sr = S + SOFF + r * 68;
        float mx = -1e30f;
#pragma unroll 8
        for (int m = 0; m < 64; m++) mx = fmaxf(mx, Sr[m]);
        float sum = 0.0f;
#pragma unroll 8
        for (int m = 0; m < 64; m++) {
            float e = __expf(Sr[m] - mx);
            sum += e;
            Sr[m] = __uint_as_float(f2tf32(e));
        }
        S[SUMOFF + r] = 1.0f / sum;
    }
    __syncthreads();

    // ---- PV : O[64x32] = P @ V ----
    float acc[2][4][4];
#pragma unroll
    for (int i = 0; i < 2; i++)
#pragma unroll
        for (int j = 0; j < 4; j++)
#pragma unroll
            for (int r = 0; r < 4; r++) acc[i][j][r] = 0.0f;

#pragma unroll
    for (int k = 0; k < 8; k++) {
        uint32_t ah[2][4];
#pragma unroll
        for (int i = 0; i < 2; i++) {
            int rb = (2 * whalf + i) * 16;
            const float* p0 = S + SOFF + (rb + g) * 68 + 8 * k + tig;
            const float* p1 = S + SOFF + (rb + 8 + g) * 68 + 8 * k + tig;
            ah[i][0] = __float_as_uint(p0[0]);
            ah[i][1] = __float_as_uint(p1[0]);
            ah[i][2] = __float_as_uint(p0[4]);
            ah[i][3] = __float_as_uint(p1[4]);
        }
        uint32_t bf[4][2];
#pragma unroll
        for (int j = 0; j < 4; j++) {
            const float* v0 = S + VOFF + (8 * k + tig) * 40 + 8 * j + g;
            const float* v1 = S + VOFF + (8 * k + tig + 4) * 40 + 8 * j + g;
            bf[j][0] = __float_as_uint(v0[0]);
            bf[j][1] = __float_as_uint(v1[0]);
        }
#pragma unroll
        for (int i = 0; i < 2; i++)
#pragma unroll
            for (int j = 0; j < 4; j++)
                mma_tf32(acc[i][j], ah[i], bf[j]);
    }

    // ---- epilogue ----
    float* og = g_attn + (size_t)((b * 2 + t) * 64) * 256 + h * 32;
#pragma unroll
    for (int i = 0; i < 2; i++) {
        int rb = (2 * whalf + i) * 16;
        float is0 = S[SUMOFF + rb + g];
        float is1 = S[SUMOFF + rb + 8 + g];
#pragma unroll
        for (int j = 0; j < 4; j++) {
            int d = 8 * j + 2 * tig;
            *reinterpret_cast<float2*>(og + (size_t)(rb + g) * 256 + d) =
                make_float2(acc[i][j][0] * is0, acc[i][j][1] * is0);
            *reinterpret_cast<float2*>(og + (size_t)(rb + 8 + g) * 256 + d) =
                make_float2(acc[i][j][2] * is1, acc[i][j][3] * is1);
        }
    }
}

// ---------------------------------------------------------------------------
extern "C" void kernel_launch(void* const* d_in, const int* in_sizes, int n_in,
                              void* d_out, int out_size)
{
    const float* x      = (const float*)d_in[0];
    const float* memory = (const float*)d_in[1];
    const float* q_w    = (const float*)d_in[2];
    const float* q_b    = (const float*)d_in[3];
    const float* kv_w   = (const float*)d_in[4];
    const float* kv_b   = (const float*)d_in[5];
    const float* proj_w = (const float*)d_in[6];
    const float* proj_b = (const float*)d_in[7];
    const float* rpb    = (const float*)d_in[8];
    float* out = (float*)d_out;

    float *pq, *pkv, *pattn, *pwq, *pwkv, *pwp;
    cudaGetSymbolAddress((void**)&pq, g_q);
    cudaGetSymbolAddress((void**)&pkv, g_kv);
    cudaGetSymbolAddress((void**)&pattn, g_attn);
    cudaGetSymbolAddress((void**)&pwq, g_wq);
    cudaGetSymbolAddress((void**)&pwkv, g_wkv);
    cudaGetSymbolAddress((void**)&pwp, g_wp);

    cudaFuncSetAttribute(gemm_tf32, cudaFuncAttributeMaxDynamicSharedMemorySize,
                         GEMM_SMEM_BYTES);
    cudaFuncSetAttribute(attn_mma, cudaFuncAttributeMaxDynamicSharedMemorySize,
                         ATTN_SMEM_BYTES);

    bias_precomp<<<128, 256>>>(rpb);
    wconv<<<(CDIM * CDIM + 255) / 256, 256>>>(q_w, pwq, CDIM * CDIM);
    wconv<<<(2 * CDIM * CDIM + 255) / 256, 256>>>(kv_w, pwkv, 2 * CDIM * CDIM);
    wconv<<<(CDIM * CDIM + 255) / 256, 256>>>(proj_w, pwp, CDIM * CDIM);

    // q = x @ q_w^T + q_b              (131072 x 256, K=256)  grid (2, 512)
    gemm_tf32<<<dim3(2, 512), 256, GEMM_SMEM_BYTES>>>(x, pwq, q_b, pq, BB * NTOK, CDIM, CDIM);
    // kv = memory @ kv_w^T + kv_b      (262144 x 512, K=256)  grid (4, 1024)
    gemm_tf32<<<dim3(4, 1024), 256, GEMM_SMEM_BYTES>>>(memory, pwkv, kv_b, pkv, BB * TT * NTOK, 2 * CDIM, CDIM);
    // attention: block = (b, t, head-pair)
    attn_mma<<<BB * TT * (NH / 2), 128, ATTN_SMEM_BYTES>>>();
    // out = attn @ proj_w^T + proj_b   (262144 x 256, K=256)  grid (2, 1024)
    gemm_tf32<<<dim3(2, 1024), 256, GEMM_SMEM_BYTES>>>(pattn, pwp, proj_b, out, BB * TT * NTOK, CDIM, CDIM);
}